// round 5
// baseline (speedup 1.0000x reference)
#include <cuda_runtime.h>
#include <math.h>

#define NPTS 2048
#define DIN  768
#define DOUT 64
#define NMAT 7
// ln(2048) to double precision; compiler rounds to the same float32 JAX uses
#define LN_N 7.624618986159398f

// ---------------------------------------------------------------------------
// Device scratch (static globals — no allocation in kernel_launch)
// ---------------------------------------------------------------------------
__device__ float d_Wt[DIN * DOUT];            // W transposed: [768][64]
__device__ float d_P[3][NPTS * DOUT];         // pd, p1, p2
__device__ float d_SQ[3][NPTS];               // 0.5*||row||^2
__device__ float d_C[NMAT][(size_t)NPTS * NPTS]; // 0:Cxx 1:C11 2:C22 3:Cxy1 4:Cyx1 5:Cxy2 6:Cyx2
__device__ float d_pot[2][NMAT][NPTS];        // ping-pong potentials per "pass slot"
__device__ float d_potF[NMAT][NPTS];          // final potentials

// ---------------------------------------------------------------------------
// W transpose:  Wt[j][k] = W[k][j]
// ---------------------------------------------------------------------------
__global__ void k_transposeW(const float* __restrict__ W) {
    int e = blockIdx.x * blockDim.x + threadIdx.x;
    if (e < DIN * DOUT) {
        int j = e / DOUT, k = e % DOUT;
        d_Wt[e] = W[k * DIN + j];
    }
}

// ---------------------------------------------------------------------------
// predict: P = relu(X @ W^T + b), 64x64 output tile per block, K-chunks of 64
// ---------------------------------------------------------------------------
__global__ __launch_bounds__(256) void k_predict(const float* __restrict__ X0,
                                                 const float* __restrict__ X1,
                                                 const float* __restrict__ X2,
                                                 const float* __restrict__ bias) {
    __shared__ float Xs[64 * 65];
    __shared__ float Ws[64 * 64];
    const float* X = (blockIdx.y == 0) ? X0 : (blockIdx.y == 1) ? X1 : X2;
    int rowBase = blockIdx.x * 64;
    int tid = threadIdx.x;
    int ty = tid >> 4, tx = tid & 15;

    float acc[4][4];
#pragma unroll
    for (int i = 0; i < 4; i++)
#pragma unroll
        for (int j = 0; j < 4; j++) acc[i][j] = 0.f;

    for (int k0 = 0; k0 < DIN; k0 += 64) {
#pragma unroll
        for (int i = 0; i < 16; i++) {
            int e = tid + i * 256;
            int r = e >> 6, c = e & 63;
            Xs[r * 65 + c] = X[(size_t)(rowBase + r) * DIN + k0 + c];
            Ws[r * 64 + c] = d_Wt[(k0 + r) * DOUT + c];
        }
        __syncthreads();
#pragma unroll
        for (int kk = 0; kk < 64; kk++) {
            float a[4], b[4];
#pragma unroll
            for (int i = 0; i < 4; i++) a[i] = Xs[(ty * 4 + i) * 65 + kk];
#pragma unroll
            for (int j = 0; j < 4; j++) b[j] = Ws[kk * 64 + tx * 4 + j];
#pragma unroll
            for (int i = 0; i < 4; i++)
#pragma unroll
                for (int j = 0; j < 4; j++) acc[i][j] = fmaf(a[i], b[j], acc[i][j]);
        }
        __syncthreads();
    }

#pragma unroll
    for (int i = 0; i < 4; i++)
#pragma unroll
        for (int j = 0; j < 4; j++) {
            float v = acc[i][j] + bias[tx * 4 + j];
            v = fmaxf(v, 0.f);
            d_P[blockIdx.y][(rowBase + ty * 4 + i) * DOUT + tx * 4 + j] = v;
        }
}

// ---------------------------------------------------------------------------
// 0.5 * ||row||^2 for each of the 3*2048 projected points. One warp per row.
// ---------------------------------------------------------------------------
__global__ void k_sqnorm() {
    int wid = threadIdx.x >> 5, lane = threadIdx.x & 31;
    int grow = blockIdx.x * 8 + wid;            // 0..6143
    int b = grow >> 11, r = grow & (NPTS - 1);
    float v0 = d_P[b][r * DOUT + lane];
    float v1 = d_P[b][r * DOUT + 32 + lane];
    float v = v0 * v0 + v1 * v1;
#pragma unroll
    for (int off = 16; off > 0; off >>= 1)
        v += __shfl_xor_sync(0xffffffffu, v, off);
    if (lane == 0) d_SQ[b][r] = 0.5f * v;
}

// ---------------------------------------------------------------------------
// cost: C[i][j] = 0.5||a_i||^2 + 0.5||b_j||^2 - a_i . b_j   (K = 64)
// Writes row-major into d_C[ci]; optionally writes the transpose into d_C[ti].
// ---------------------------------------------------------------------------
__global__ __launch_bounds__(256) void k_cost(int ai, int bi, int ci, int ti) {
    __shared__ float sA[64 * 65];
    __shared__ float sB[64 * 65];
    const float* A = d_P[ai];
    const float* B = d_P[bi];
    int i0 = blockIdx.y * 64, j0 = blockIdx.x * 64;
    int tid = threadIdx.x, ty = tid >> 4, tx = tid & 15;

#pragma unroll
    for (int i = 0; i < 16; i++) {
        int e = tid + i * 256;
        int r = e >> 6, c = e & 63;
        sA[r * 65 + c] = A[(i0 + r) * DOUT + c];
        sB[r * 65 + c] = B[(j0 + r) * DOUT + c];
    }
    __syncthreads();

    float acc[4][4];
#pragma unroll
    for (int i = 0; i < 4; i++)
#pragma unroll
        for (int j = 0; j < 4; j++) acc[i][j] = 0.f;

#pragma unroll
    for (int kk = 0; kk < 64; kk++) {
        float a[4], b[4];
#pragma unroll
        for (int i = 0; i < 4; i++) a[i] = sA[(ty * 4 + i) * 65 + kk];
#pragma unroll
        for (int j = 0; j < 4; j++) b[j] = sB[(tx * 4 + j) * 65 + kk];
#pragma unroll
        for (int i = 0; i < 4; i++)
#pragma unroll
            for (int j = 0; j < 4; j++) acc[i][j] = fmaf(a[i], b[j], acc[i][j]);
    }

    float sqa[4], sqb[4];
#pragma unroll
    for (int i = 0; i < 4; i++) sqa[i] = d_SQ[ai][i0 + ty * 4 + i];
#pragma unroll
    for (int j = 0; j < 4; j++) sqb[j] = d_SQ[bi][j0 + tx * 4 + j];

    float val[4][4];
    float* Cm = d_C[ci];
#pragma unroll
    for (int i = 0; i < 4; i++)
#pragma unroll
        for (int j = 0; j < 4; j++) {
            val[i][j] = sqa[i] + sqb[j] - acc[i][j];
            Cm[(size_t)(i0 + ty * 4 + i) * NPTS + j0 + tx * 4 + j] = val[i][j];
        }

    if (ti >= 0) {
        __syncthreads();            // everyone done reading sA
#pragma unroll
        for (int i = 0; i < 4; i++)
#pragma unroll
            for (int j = 0; j < 4; j++)
                sA[(tx * 4 + j) * 65 + ty * 4 + i] = val[i][j];
        __syncthreads();
        float* Ct = d_C[ti];
#pragma unroll
        for (int i = 0; i < 16; i++) {
            int e = tid + i * 256;
            int r = e >> 6, c = e & 63;
            Ct[(size_t)(j0 + r) * NPTS + i0 + c] = sA[r * 65 + c];
        }
    }
}

// ---------------------------------------------------------------------------
// zero the ping-pong potential buffers
// ---------------------------------------------------------------------------
__global__ void k_init() {
    int e = blockIdx.x * blockDim.x + threadIdx.x;
    if (e < 2 * NMAT * NPTS) (&d_pot[0][0][0])[e] = 0.f;
}

// ---------------------------------------------------------------------------
// One Sinkhorn scan step fused across all 7 passes:
//   slots 0..2: XX problems (vin = own f), slots 3/4 and 5/6: XY (f,g) pairs.
// f_i = eps*(ln N - LSE_j((vin_j - C_ij)/eps));  out = avg ? 0.5*(old+ft) : ft
// One warp per row; row cached in registers (2 chunks of 32), online LSE.
// ---------------------------------------------------------------------------
__global__ __launch_bounds__(512) void k_step(int cur, float eps, int avg, int fin) {
    __shared__ float sg[NPTS];
    const int nxt = cur ^ 1;
    const int pp = blockIdx.x >> 7;                       // 128 blocks per pass
    const int rowbase = (blockIdx.x & 127) * 16;
    const int vinSlot = (pp < 3) ? pp : (((pp - 3) ^ 1) + 3); // swap f<->g for XY
    const float* __restrict__ vin  = d_pot[cur][vinSlot];
    const float* __restrict__ favg = d_pot[cur][pp];
    float* __restrict__ out = fin ? d_potF[pp] : d_pot[nxt][pp];
    const float* __restrict__ Cm = d_C[pp];
    const float inv_eps = 1.0f / eps;
    const float nie = -inv_eps;

    for (int j = threadIdx.x; j < NPTS; j += 512)
        sg[j] = vin[j] * inv_eps;
    __syncthreads();

    const int wid = threadIdx.x >> 5, lane = threadIdx.x & 31;
    const int row = rowbase + wid;
    const float* __restrict__ Crow = Cm + (size_t)row * NPTS;

    float xv[32];
    float m1 = -3.4e38f;
#pragma unroll
    for (int k = 0; k < 32; k++) {
        int j = k * 32 + lane;
        float t = fmaf(Crow[j], nie, sg[j]);
        xv[k] = t;
        m1 = fmaxf(m1, t);
    }
    float s1 = 0.f;
#pragma unroll
    for (int k = 0; k < 32; k++) s1 += __expf(xv[k] - m1);

    float m2 = -3.4e38f;
#pragma unroll
    for (int k = 0; k < 32; k++) {
        int j = 1024 + k * 32 + lane;
        float t = fmaf(Crow[j], nie, sg[j]);
        xv[k] = t;
        m2 = fmaxf(m2, t);
    }
    float s2 = 0.f;
#pragma unroll
    for (int k = 0; k < 32; k++) s2 += __expf(xv[k] - m2);

    float m = fmaxf(m1, m2);
    float s = s1 * __expf(m1 - m) + s2 * __expf(m2 - m);

#pragma unroll
    for (int off = 16; off > 0; off >>= 1) {
        float mo = __shfl_xor_sync(0xffffffffu, m, off);
        float so = __shfl_xor_sync(0xffffffffu, s, off);
        float mn = fmaxf(m, mo);
        s = s * __expf(m - mn) + so * __expf(mo - mn);
        m = mn;
    }

    if (lane == 0) {
        float ft = eps * (LN_N - (m + __logf(s)));
        out[row] = avg ? 0.5f * (favg[row] + ft) : ft;
    }
}

// ---------------------------------------------------------------------------
// dist1 = <a, f_xy1 - f_xx> + <b, g_xy1 - g_y1y1>, dist2 analogous.
// out = sigmoid(10 * (dist2 - dist1))
// ---------------------------------------------------------------------------
__global__ void k_reduce(float* out) {
    __shared__ float s1h[256], s2h[256];
    int t = threadIdx.x;
    float a1 = 0.f, a2 = 0.f;
    for (int i = t; i < NPTS; i += 256) {
        float fxx = d_potF[0][i];
        a1 += (d_potF[3][i] - fxx) + (d_potF[4][i] - d_potF[1][i]);
        a2 += (d_potF[5][i] - fxx) + (d_potF[6][i] - d_potF[2][i]);
    }
    s1h[t] = a1;
    s2h[t] = a2;
    __syncthreads();
    for (int off = 128; off > 0; off >>= 1) {
        if (t < off) { s1h[t] += s1h[t + off]; s2h[t] += s2h[t + off]; }
        __syncthreads();
    }
    if (t == 0) {
        const float inv = 1.0f / (float)NPTS;
        float dist1 = s1h[0] * inv;
        float dist2 = s2h[0] * inv;
        float z = 10.0f * (dist2 - dist1);
        out[0] = 1.0f / (1.0f + expf(-z));
    }
}

// ---------------------------------------------------------------------------
// Launcher (graph-capturable: kernel launches only)
// ---------------------------------------------------------------------------
extern "C" void kernel_launch(void* const* d_in, const int* in_sizes, int n_in,
                              void* d_out, int out_size) {
    (void)in_sizes; (void)n_in; (void)out_size;
    const float* dX = (const float*)d_in[0];
    const float* s1 = (const float*)d_in[1];
    const float* s2 = (const float*)d_in[2];
    const float* W  = (const float*)d_in[3];
    const float* bb = (const float*)d_in[4];
    float* out = (float*)d_out;

    k_transposeW<<<(DIN * DOUT + 255) / 256, 256>>>(W);
    k_predict<<<dim3(NPTS / 64, 3), 256>>>(dX, s1, s2, bb);
    k_sqnorm<<<3 * NPTS / 8, 256>>>();

    // cost matrices: Cxx, C11, C22, Cxy1(+T), Cxy2(+T)
    k_cost<<<dim3(32, 32), 256>>>(0, 0, 0, -1);
    k_cost<<<dim3(32, 32), 256>>>(1, 1, 1, -1);
    k_cost<<<dim3(32, 32), 256>>>(2, 2, 2, -1);
    k_cost<<<dim3(32, 32), 256>>>(0, 1, 3, 4);
    k_cost<<<dim3(32, 32), 256>>>(0, 2, 5, 6);

    k_init<<<(2 * NMAT * NPTS + 255) / 256, 256>>>();

    // epsilon schedule (geomloss-style), computed in double and cast to float
    // exactly as numpy/jax do
    const double eps0 = 32.0;
    const double epsf = pow(0.05, 2.0);       // BLUR**P
    const double ratio = pow(0.9, 2.0);       // SCALING**P
    int n = (int)ceil(log(epsf / eps0) / log(ratio));   // 45
    float sched[64];
    int cnt = 0;
    for (int k = 0; k <= n; k++) {
        double v = eps0 * pow(ratio, (double)k);
        if (v < epsf) v = epsf;
        sched[cnt++] = (float)v;
    }
    sched[cnt++] = (float)epsf;               // cnt = 47

    for (int k = 0; k < cnt; k++)
        k_step<<<NMAT * 128, 512>>>(k & 1, sched[k], 1, 0);

    // final differentiable update at eps_f (no averaging, write final arrays)
    k_step<<<NMAT * 128, 512>>>(cnt & 1, (float)epsf, 0, 1);

    k_reduce<<<1, 256>>>(out);
}

// round 6
// speedup vs baseline: 1.1159x; 1.1159x over previous
#include <cuda_runtime.h>
#include <math.h>

#define NPTS 2048
#define DIN  768
#define DOUT 64
#define NMAT 7
#define LN_N   7.624618986159398f      // ln(2048)
#define LOG2E  1.4426950408889634f
#define LN2    0.6931471805599453f

// ---------------------------------------------------------------------------
// Device scratch (static globals — no allocation in kernel_launch)
// ---------------------------------------------------------------------------
__device__ __align__(16) float d_Wt[DIN * DOUT];             // W^T: [768][64]
__device__ __align__(16) float d_P[3][NPTS * DOUT];          // pd, p1, p2
__device__ __align__(16) float d_SQ[3][NPTS];                // 0.5*||row||^2
__device__ __align__(16) float d_C[NMAT][(size_t)NPTS * NPTS];
// 0:Cxx 1:C11 2:C22 3:Cxy1 4:Cyx1 5:Cxy2 6:Cyx2
__device__ __align__(16) float d_pot[2][NMAT][NPTS];         // ping-pong potentials
__device__ __align__(16) float d_potF[NMAT][NPTS];           // final potentials

__constant__ int cAi[5] = {0, 1, 2, 0, 0};
__constant__ int cBi[5] = {0, 1, 2, 1, 2};
__constant__ int cCi[5] = {0, 1, 2, 3, 5};
__constant__ int cTi[5] = {-1, -1, -1, 4, 6};

__device__ __forceinline__ float ex2f(float x) {
    float r; asm("ex2.approx.ftz.f32 %0, %1;" : "=f"(r) : "f"(x)); return r;
}
__device__ __forceinline__ float lg2f(float x) {
    float r; asm("lg2.approx.f32 %0, %1;" : "=f"(r) : "f"(x)); return r;
}

// ---------------------------------------------------------------------------
// W transpose:  Wt[j][k] = W[k][j]
// ---------------------------------------------------------------------------
__global__ void k_transposeW(const float* __restrict__ W) {
    int e = blockIdx.x * blockDim.x + threadIdx.x;
    if (e < DIN * DOUT) {
        int j = e / DOUT, k = e % DOUT;
        d_Wt[e] = W[k * DIN + j];
    }
}

// ---------------------------------------------------------------------------
// predict: P = relu(X @ W^T + b). 64x64 tile / 256 threads, smem in [k][row]
// layout so operand fetches are LDS.128.
// ---------------------------------------------------------------------------
__global__ __launch_bounds__(256) void k_predict(const float* __restrict__ X0,
                                                 const float* __restrict__ X1,
                                                 const float* __restrict__ X2,
                                                 const float* __restrict__ bias) {
    __shared__ __align__(16) float Xs[64 * 68];   // [kk][row]
    __shared__ __align__(16) float Ws[64 * 64];   // [kk][col]
    const float* X = (blockIdx.y == 0) ? X0 : (blockIdx.y == 1) ? X1 : X2;
    int rowBase = blockIdx.x * 64;
    int tid = threadIdx.x;
    int ty = tid >> 4, tx = tid & 15;

    float acc[4][4];
#pragma unroll
    for (int i = 0; i < 4; i++)
#pragma unroll
        for (int j = 0; j < 4; j++) acc[i][j] = 0.f;

    for (int k0 = 0; k0 < DIN; k0 += 64) {
#pragma unroll
        for (int i = 0; i < 16; i++) {
            int e = tid + i * 256;
            int r = e >> 6, c = e & 63;
            Xs[c * 68 + r] = X[(size_t)(rowBase + r) * DIN + k0 + c];
            Ws[r * 64 + c] = d_Wt[(k0 + r) * DOUT + c];
        }
        __syncthreads();
#pragma unroll
        for (int kk = 0; kk < 64; kk++) {
            float4 a = *reinterpret_cast<const float4*>(&Xs[kk * 68 + ty * 4]);
            float4 b = *reinterpret_cast<const float4*>(&Ws[kk * 64 + tx * 4]);
            float av[4] = {a.x, a.y, a.z, a.w};
            float bv[4] = {b.x, b.y, b.z, b.w};
#pragma unroll
            for (int i = 0; i < 4; i++)
#pragma unroll
                for (int j = 0; j < 4; j++) acc[i][j] = fmaf(av[i], bv[j], acc[i][j]);
        }
        __syncthreads();
    }

#pragma unroll
    for (int i = 0; i < 4; i++)
#pragma unroll
        for (int j = 0; j < 4; j++) {
            float v = acc[i][j] + bias[tx * 4 + j];
            v = fmaxf(v, 0.f);
            d_P[blockIdx.y][(rowBase + ty * 4 + i) * DOUT + tx * 4 + j] = v;
        }
}

// ---------------------------------------------------------------------------
// 0.5 * ||row||^2, one warp per row
// ---------------------------------------------------------------------------
__global__ void k_sqnorm() {
    int wid = threadIdx.x >> 5, lane = threadIdx.x & 31;
    int grow = blockIdx.x * 8 + wid;
    int b = grow >> 11, r = grow & (NPTS - 1);
    float v0 = d_P[b][r * DOUT + lane];
    float v1 = d_P[b][r * DOUT + 32 + lane];
    float v = v0 * v0 + v1 * v1;
#pragma unroll
    for (int off = 16; off > 0; off >>= 1)
        v += __shfl_xor_sync(0xffffffffu, v, off);
    if (lane == 0) d_SQ[b][r] = 0.5f * v;
}

// ---------------------------------------------------------------------------
// cost: C[i][j] = 0.5||a_i||^2 + 0.5||b_j||^2 - a_i . b_j  (K=64)
// All 5 cost matrices in one launch (blockIdx.z). Transposed copy optional.
// ---------------------------------------------------------------------------
__global__ __launch_bounds__(256) void k_cost() {
    __shared__ __align__(16) float sA[64 * 68];   // [kk][row]
    __shared__ __align__(16) float sB[64 * 68];   // [kk][col]
    const int z = blockIdx.z;
    const int ai = cAi[z], bi = cBi[z], ci = cCi[z], ti = cTi[z];
    const float* A = d_P[ai];
    const float* B = d_P[bi];
    int i0 = blockIdx.y * 64, j0 = blockIdx.x * 64;
    int tid = threadIdx.x, ty = tid >> 4, tx = tid & 15;

#pragma unroll
    for (int i = 0; i < 16; i++) {
        int e = tid + i * 256;
        int r = e >> 6, c = e & 63;
        sA[c * 68 + r] = A[(i0 + r) * DOUT + c];
        sB[c * 68 + r] = B[(j0 + r) * DOUT + c];
    }
    __syncthreads();

    float acc[4][4];
#pragma unroll
    for (int i = 0; i < 4; i++)
#pragma unroll
        for (int j = 0; j < 4; j++) acc[i][j] = 0.f;

#pragma unroll
    for (int kk = 0; kk < 64; kk++) {
        float4 a = *reinterpret_cast<const float4*>(&sA[kk * 68 + ty * 4]);
        float4 b = *reinterpret_cast<const float4*>(&sB[kk * 68 + tx * 4]);
        float av[4] = {a.x, a.y, a.z, a.w};
        float bv[4] = {b.x, b.y, b.z, b.w};
#pragma unroll
        for (int i = 0; i < 4; i++)
#pragma unroll
            for (int j = 0; j < 4; j++) acc[i][j] = fmaf(av[i], bv[j], acc[i][j]);
    }

    float sqa[4], sqb[4];
#pragma unroll
    for (int i = 0; i < 4; i++) sqa[i] = d_SQ[ai][i0 + ty * 4 + i];
#pragma unroll
    for (int j = 0; j < 4; j++) sqb[j] = d_SQ[bi][j0 + tx * 4 + j];

    float val[4][4];
    float* Cm = d_C[ci];
#pragma unroll
    for (int i = 0; i < 4; i++)
#pragma unroll
        for (int j = 0; j < 4; j++) {
            val[i][j] = sqa[i] + sqb[j] - acc[i][j];
            Cm[(size_t)(i0 + ty * 4 + i) * NPTS + j0 + tx * 4 + j] = val[i][j];
        }

    if (ti >= 0) {
        __syncthreads();            // done reading sA
#pragma unroll
        for (int i = 0; i < 4; i++)
#pragma unroll
            for (int j = 0; j < 4; j++)
                sA[(tx * 4 + j) * 65 + ty * 4 + i] = val[i][j];
        __syncthreads();
        float* Ct = d_C[ti];
#pragma unroll
        for (int i = 0; i < 16; i++) {
            int e = tid + i * 256;
            int r = e >> 6, c = e & 63;
            Ct[(size_t)(j0 + r) * NPTS + i0 + c] = sA[r * 65 + c];
        }
    }
}

// ---------------------------------------------------------------------------
// zero ping-pong potential buffers
// ---------------------------------------------------------------------------
__global__ void k_init() {
    int e = blockIdx.x * blockDim.x + threadIdx.x;
    if (e < 2 * NMAT * NPTS) (&d_pot[0][0][0])[e] = 0.f;
}

// ---------------------------------------------------------------------------
// One fused Sinkhorn scan step across all 7 passes. 256 threads = 8 rows.
// f_i = eps*(ln N - ln2 * LSE2_j[(vin_j - C_ij)*log2e/eps])   (base-2 domain)
// Lane l owns j in {128k + 4l .. +3}: LDG.128 / LDS.128, fully coalesced.
// ---------------------------------------------------------------------------
__global__ __launch_bounds__(256) void k_step(int cur, float eps, int avg, int fin) {
    __shared__ float4 sg4[NPTS / 4];
    const int nxt = cur ^ 1;
    const int pp = blockIdx.x >> 8;                        // 256 blocks / pass
    const int rowbase = (blockIdx.x & 255) * 8;
    const int vinSlot = (pp < 3) ? pp : (((pp - 3) ^ 1) + 3);
    const float* __restrict__ vin  = d_pot[cur][vinSlot];
    const float* __restrict__ favg = d_pot[cur][pp];
    float* __restrict__ out = fin ? d_potF[pp] : d_pot[nxt][pp];
    const float* __restrict__ Cm = d_C[pp];
    const float pscale = LOG2E / eps;                      // +1/eps in log2 dom
    const float nscale = -pscale;

    // stage vin/eps*log2e into shared (float4)
    const float4* vin4 = reinterpret_cast<const float4*>(vin);
    for (int j = threadIdx.x; j < NPTS / 4; j += 256) {
        float4 v = vin4[j];
        v.x *= pscale; v.y *= pscale; v.z *= pscale; v.w *= pscale;
        sg4[j] = v;
    }
    __syncthreads();

    const int wid = threadIdx.x >> 5, lane = threadIdx.x & 31;
    const int row = rowbase + wid;
    const float4* __restrict__ Crow4 =
        reinterpret_cast<const float4*>(Cm + (size_t)row * NPTS);

    float4 xv[8];
    // ---- chunk 1: float4 indices 0..255 (j 0..1023) ----
    float m1 = -3.4e38f;
#pragma unroll
    for (int k = 0; k < 8; k++) {
        float4 c = Crow4[k * 32 + lane];
        float4 g = sg4[k * 32 + lane];
        float4 t;
        t.x = fmaf(c.x, nscale, g.x);
        t.y = fmaf(c.y, nscale, g.y);
        t.z = fmaf(c.z, nscale, g.z);
        t.w = fmaf(c.w, nscale, g.w);
        xv[k] = t;
        m1 = fmaxf(m1, fmaxf(fmaxf(t.x, t.y), fmaxf(t.z, t.w)));
    }
    float s1 = 0.f;
#pragma unroll
    for (int k = 0; k < 8; k++) {
        s1 += ex2f(xv[k].x - m1) + ex2f(xv[k].y - m1)
            + ex2f(xv[k].z - m1) + ex2f(xv[k].w - m1);
    }
    // ---- chunk 2: float4 indices 256..511 (j 1024..2047) ----
    float m2 = -3.4e38f;
#pragma unroll
    for (int k = 0; k < 8; k++) {
        float4 c = Crow4[256 + k * 32 + lane];
        float4 g = sg4[256 + k * 32 + lane];
        float4 t;
        t.x = fmaf(c.x, nscale, g.x);
        t.y = fmaf(c.y, nscale, g.y);
        t.z = fmaf(c.z, nscale, g.z);
        t.w = fmaf(c.w, nscale, g.w);
        xv[k] = t;
        m2 = fmaxf(m2, fmaxf(fmaxf(t.x, t.y), fmaxf(t.z, t.w)));
    }
    float s2 = 0.f;
#pragma unroll
    for (int k = 0; k < 8; k++) {
        s2 += ex2f(xv[k].x - m2) + ex2f(xv[k].y - m2)
            + ex2f(xv[k].z - m2) + ex2f(xv[k].w - m2);
    }

    float m = fmaxf(m1, m2);
    float s = s1 * ex2f(m1 - m) + s2 * ex2f(m2 - m);

#pragma unroll
    for (int off = 16; off > 0; off >>= 1) {
        float mo = __shfl_xor_sync(0xffffffffu, m, off);
        float so = __shfl_xor_sync(0xffffffffu, s, off);
        float mn = fmaxf(m, mo);
        s = s * ex2f(m - mn) + so * ex2f(mo - mn);
        m = mn;
    }

    if (lane == 0) {
        float ft = eps * (LN_N - (m + lg2f(s)) * LN2);
        out[row] = avg ? 0.5f * (favg[row] + ft) : ft;
    }
}

// ---------------------------------------------------------------------------
// dist1 = <a, f_xy1 - f_xx> + <b, g_xy1 - g_y1y1>, dist2 analogous.
// out = sigmoid(10 * (dist2 - dist1))
// ---------------------------------------------------------------------------
__global__ void k_reduce(float* out) {
    __shared__ float s1h[256], s2h[256];
    int t = threadIdx.x;
    float a1 = 0.f, a2 = 0.f;
    for (int i = t; i < NPTS; i += 256) {
        float fxx = d_potF[0][i];
        a1 += (d_potF[3][i] - fxx) + (d_potF[4][i] - d_potF[1][i]);
        a2 += (d_potF[5][i] - fxx) + (d_potF[6][i] - d_potF[2][i]);
    }
    s1h[t] = a1;
    s2h[t] = a2;
    __syncthreads();
    for (int off = 128; off > 0; off >>= 1) {
        if (t < off) { s1h[t] += s1h[t + off]; s2h[t] += s2h[t + off]; }
        __syncthreads();
    }
    if (t == 0) {
        const float inv = 1.0f / (float)NPTS;
        float dist1 = s1h[0] * inv;
        float dist2 = s2h[0] * inv;
        float z = 10.0f * (dist2 - dist1);
        out[0] = 1.0f / (1.0f + expf(-z));
    }
}

// ---------------------------------------------------------------------------
// Launcher (graph-capturable: kernel launches only)
// ---------------------------------------------------------------------------
extern "C" void kernel_launch(void* const* d_in, const int* in_sizes, int n_in,
                              void* d_out, int out_size) {
    (void)in_sizes; (void)n_in; (void)out_size;
    const float* dX = (const float*)d_in[0];
    const float* s1 = (const float*)d_in[1];
    const float* s2 = (const float*)d_in[2];
    const float* W  = (const float*)d_in[3];
    const float* bb = (const float*)d_in[4];
    float* out = (float*)d_out;

    k_transposeW<<<(DIN * DOUT + 255) / 256, 256>>>(W);
    k_predict<<<dim3(NPTS / 64, 3), 256>>>(dX, s1, s2, bb);
    k_sqnorm<<<3 * NPTS / 8, 256>>>();
    k_cost<<<dim3(32, 32, 5), 256>>>();
    k_init<<<(2 * NMAT * NPTS + 255) / 256, 256>>>();

    // epsilon schedule (geomloss-style), computed in double, cast to float
    const double eps0 = 32.0;
    const double epsf = pow(0.05, 2.0);
    const double ratio = pow(0.9, 2.0);
    int n = (int)ceil(log(epsf / eps0) / log(ratio));   // 45
    float sched[64];
    int cnt = 0;
    for (int k = 0; k <= n; k++) {
        double v = eps0 * pow(ratio, (double)k);
        if (v < epsf) v = epsf;
        sched[cnt++] = (float)v;
    }
    sched[cnt++] = (float)epsf;                          // cnt = 47

    for (int k = 0; k < cnt; k++)
        k_step<<<NMAT * 256, 256>>>(k & 1, sched[k], 1, 0);

    // final differentiable update at eps_f (no averaging, write final arrays)
    k_step<<<NMAT * 256, 256>>>(cnt & 1, (float)epsf, 0, 1);

    k_reduce<<<1, 256>>>(out);
}